// round 5
// baseline (speedup 1.0000x reference)
#include <cuda_runtime.h>
#include <math.h>
#include <stdint.h>

#define NINS   2048
#define TOK    16
#define EMB    512
#define HID    256
#define G4     (4*HID)      // 1024
#define PAR    8
#define LEVELS 16
#define KROWS  (NINS/LEVELS) // 128
#define T_PAD  20

// ---------------- scratch (static device globals; no allocation) ----------------
__device__ float g_Xp[NINS*TOK*G4];      // 128 MiB token input projections
__device__ float g_H[NINS*HID];
__device__ float g_C[NINS*HID];
__device__ float g_H2[NINS*HID];
__device__ float g_C2[NINS*HID];
__device__ float g_Gx[NINS*G4];
__device__ float g_Hi[NINS*HID];
__device__ float g_Ci[NINS*HID];
__device__ float g_h0[KROWS*HID];
__device__ float g_c0[KROWS*HID];
__device__ float g_WhhTokP[G4*HID];      // gate-interleaved, tf32-rounded
__device__ float g_WhhInsP[G4*HID];
__device__ float g_WihTokR[G4*EMB];      // tf32-rounded copy
__device__ float g_WihInsR[G4*HID];
__device__ unsigned char g_pval[NINS*PAR];
__device__ int   g_appears[NINS];
__device__ float g_partial[64*HID];
__device__ unsigned int g_bar2;
__device__ unsigned int g_bar3;

// ---------------- tf32 helpers ----------------
__device__ __forceinline__ uint32_t cvt_tf32(float v) {
    uint32_t r;
    asm("cvt.rna.tf32.f32 %0, %1;" : "=r"(r) : "f"(v));
    return r;
}
__device__ __forceinline__ void mma_tf32(float* c, uint32_t a0, uint32_t a1,
                                         uint32_t a2, uint32_t a3,
                                         uint32_t b0, uint32_t b1) {
    asm("mma.sync.aligned.m16n8k8.row.col.f32.tf32.tf32.f32 "
        "{%0,%1,%2,%3}, {%4,%5,%6,%7}, {%8,%9}, {%0,%1,%2,%3};"
        : "+f"(c[0]), "+f"(c[1]), "+f"(c[2]), "+f"(c[3])
        : "r"(a0), "r"(a1), "r"(a2), "r"(a3), "r"(b0), "r"(b1));
}
__device__ __forceinline__ void cp_async16(void* smem, const void* gmem) {
    uint32_t s = (uint32_t)__cvta_generic_to_shared(smem);
    asm volatile("cp.async.cg.shared.global [%0], [%1], 16;\n" :: "r"(s), "l"(gmem));
}

// ---------------- grid barrier for persistent kernels ----------------
__device__ __forceinline__ void grid_sync(unsigned int* bar, unsigned int target) {
    __threadfence();
    __syncthreads();
    if (threadIdx.x == 0) {
        atomicAdd(bar, 1u);
        while (atomicAdd(bar, 0u) < target) { __nanosleep(32); }
    }
    __syncthreads();
    __threadfence();
}

// ---------------- prep ----------------
__global__ void prep_kernel(const unsigned char* __restrict__ pv_raw,
                            const int* __restrict__ pidx)
{
    __shared__ int s_hi, s_b0;
    __shared__ int s_app[NINS];
    int tid = threadIdx.x;
    if (tid == 0) { g_bar2 = 0u; g_bar3 = 0u; }
    int hi = 0, b0 = 0;
    for (int i = 256 + tid; i < 4096; i += 256) {
        hi |= pv_raw[4*i+1] | pv_raw[4*i+2] | pv_raw[4*i+3];
        b0 |= pv_raw[4*i+0];
    }
    if (tid == 0) { s_hi = 0; s_b0 = 0; }
    __syncthreads();
    if (hi) atomicOr(&s_hi, 1);
    if (b0) atomicOr(&s_b0, 1);
    __syncthreads();
    int mode = (s_hi == 0) ? 0 : (s_b0 == 0 ? 1 : 2);
    for (int i = tid; i < NINS*PAR; i += 256) {
        unsigned char v;
        if (mode == 0)      v = (((const int*)pv_raw)[i]   != 0);
        else if (mode == 1) v = (((const float*)pv_raw)[i] != 0.0f);
        else                v = (pv_raw[i] != 0);
        g_pval[i] = v;
    }
    for (int i = tid; i < NINS; i += 256) s_app[i] = 0;
    __syncthreads();
    for (int i = tid; i < NINS*PAR; i += 256) {
        if (g_pval[i]) atomicAdd(&s_app[pidx[i]], 1);
    }
    __syncthreads();
    for (int i = tid; i < NINS; i += 256) g_appears[i] = s_app[i];
}

// permute weight rows to gate-interleave + round to tf32
__global__ void permW_kernel(const float* __restrict__ Win, float* __restrict__ Wout)
{
    int np = blockIdx.x;
    int n  = (np & 3) * HID + (np >> 2);
    Wout[(size_t)np * HID + threadIdx.x] =
        __uint_as_float(cvt_tf32(Win[(size_t)n * HID + threadIdx.x]));
}

// plain tf32-rounding copy
__global__ void convW_kernel(const float* __restrict__ in, float* __restrict__ out, int n)
{
    int i = blockIdx.x * blockDim.x + threadIdx.x;
    if (i < n) out[i] = __uint_as_float(cvt_tf32(in[i]));
}

// ============================================================================
// Shared tile GEMM: acc += A[bm:bm+128, :K] @ B[bn:bn+128, :K]^T
// A converted to tf32 per-fragment; B assumed pre-rounded tf32 bit patterns.
// 128x128 tile, BK=16, 2-stage cp.async pipeline, 8 warps (2x4).
// ============================================================================
template<int KDIM>
__device__ __forceinline__ void tile_gemm(
    const float* __restrict__ A, const float* __restrict__ B,
    int bm, int bn, float (&acc)[4][4][4], float* As, float* Bs)
{
    const int tid  = threadIdx.x;
    const int lane = tid & 31;
    const int warp = tid >> 5;
    const int wm = (warp >> 2) * 64;
    const int wn = (warp & 3) * 32;
    const int g   = lane >> 2;
    const int tig = lane & 3;
    const int NT = KDIM / 16;

    // prefetch stage 0
#pragma unroll
    for (int u = 0; u < 2; u++) {
        int idx = u * 256 + tid;
        int r = idx >> 2, c4 = idx & 3;
        cp_async16(As + r * T_PAD + c4 * 4, A + (size_t)(bm + r) * KDIM + c4 * 4);
        cp_async16(Bs + r * T_PAD + c4 * 4, B + (size_t)(bn + r) * KDIM + c4 * 4);
    }
    asm volatile("cp.async.commit_group;\n");

    for (int kt = 0; kt < NT; kt++) {
        int cur = kt & 1;
        if (kt + 1 < NT) {
            int nxt = (kt + 1) & 1;
            const float* Ap = A + (size_t)bm * KDIM + (kt + 1) * 16;
            const float* Bp = B + (size_t)bn * KDIM + (kt + 1) * 16;
#pragma unroll
            for (int u = 0; u < 2; u++) {
                int idx = u * 256 + tid;
                int r = idx >> 2, c4 = idx & 3;
                cp_async16(As + nxt * 128 * T_PAD + r * T_PAD + c4 * 4,
                           Ap + (size_t)r * KDIM + c4 * 4);
                cp_async16(Bs + nxt * 128 * T_PAD + r * T_PAD + c4 * 4,
                           Bp + (size_t)r * KDIM + c4 * 4);
            }
            asm volatile("cp.async.commit_group;\n");
            asm volatile("cp.async.wait_group 1;\n");
        } else {
            asm volatile("cp.async.wait_group 0;\n");
        }
        __syncthreads();

        const float* Asb = As + cur * 128 * T_PAD;
        const float* Bsb = Bs + cur * 128 * T_PAD;
#pragma unroll
        for (int ks = 0; ks < 2; ks++) {
            const int k0 = ks * 8;
            uint32_t bf[4][2];
#pragma unroll
            for (int ni = 0; ni < 4; ni++) {
                bf[ni][0] = __float_as_uint(Bsb[(wn + ni*8 + g) * T_PAD + k0 + tig]);
                bf[ni][1] = __float_as_uint(Bsb[(wn + ni*8 + g) * T_PAD + k0 + tig + 4]);
            }
            uint32_t af[4][4];
#pragma unroll
            for (int mi = 0; mi < 4; mi++) {
                int r0 = (wm + mi*16 + g) * T_PAD + k0;
                int r1 = (wm + mi*16 + 8 + g) * T_PAD + k0;
                af[mi][0] = cvt_tf32(Asb[r0 + tig]);
                af[mi][1] = cvt_tf32(Asb[r1 + tig]);
                af[mi][2] = cvt_tf32(Asb[r0 + tig + 4]);
                af[mi][3] = cvt_tf32(Asb[r1 + tig + 4]);
            }
#pragma unroll
            for (int mi = 0; mi < 4; mi++)
#pragma unroll
                for (int ni = 0; ni < 4; ni++)
                    mma_tf32(acc[mi][ni], af[mi][0], af[mi][1], af[mi][2], af[mi][3],
                             bf[ni][0], bf[ni][1]);
        }
        __syncthreads();
    }
}

// ---------------- fused LSTM epilogue (gate-interleaved B; shfl quad exchange) ----------------
__device__ __forceinline__ void fuse_epilogue(
    float (&acc)[4][4][4], int bm, int bn,
    const float* __restrict__ Add, long addStride,
    const float* __restrict__ Cprev,
    float* __restrict__ Hout, float* __restrict__ Cstate)
{
    const int lane = threadIdx.x & 31;
    const int warp = threadIdx.x >> 5;
    const int wm = (warp >> 2) * 64;
    const int wn = (warp & 3) * 32;
    const int g   = lane >> 2;
    const int tig = lane & 3;
#pragma unroll
    for (int mi = 0; mi < 4; mi++) {
#pragma unroll
        for (int ni = 0; ni < 4; ni++) {
            float c0 = acc[mi][ni][0], c1 = acc[mi][ni][1];
            float c2 = acc[mi][ni][2], c3 = acc[mi][ni][3];
            float x0 = __shfl_xor_sync(0xffffffffu, c0, 1);
            float x1 = __shfl_xor_sync(0xffffffffu, c1, 1);
            float x2 = __shfl_xor_sync(0xffffffffu, c2, 1);
            float x3 = __shfl_xor_sync(0xffffffffu, c3, 1);
            int q = tig >> 1;
            int h = (bn + wn + ni*8 + q*4) >> 2;
            int row;
            float gi, gf, gg, go;
            if ((tig & 1) == 0) {
                row = bm + wm + mi*16 + g;
                gi = c0; gf = c1; gg = x0; go = x1;
            } else {
                row = bm + wm + mi*16 + 8 + g;
                gi = x2; gf = x3; gg = c2; go = c3;
            }
            const float* ad = Add + (size_t)row * addStride;
            gi += ad[h];
            gf += ad[HID + h];
            gg += ad[2*HID + h];
            go += ad[3*HID + h];
            float c = Cprev ? Cprev[(size_t)row * HID + h] : 0.0f;
            float si = 1.0f / (1.0f + expf(-gi));
            float sf = 1.0f / (1.0f + expf(-gf));
            float so = 1.0f / (1.0f + expf(-go));
            float cn = sf * c + si * tanhf(gg);
            float hn = so * tanhf(cn);
            Cstate[(size_t)row * HID + h] = cn;
            Hout[(size_t)row * HID + h]   = hn;
        }
    }
}

// ============================================================================
// Plain GEMM kernel (phase-1 Xp and phase-3a Gx): C = A@B^T + b1 + b2
// ============================================================================
template<int KDIM>
__global__ __launch_bounds__(256, 2) void mma_plain_kernel(
    const float* __restrict__ A, const float* __restrict__ B,
    float* __restrict__ Cout,
    const float* __restrict__ b1, const float* __restrict__ b2)
{
    __shared__ float As[2*128*T_PAD];
    __shared__ float Bs[2*128*T_PAD];
    const int bm = blockIdx.y * 128;
    const int bn = blockIdx.x * 128;
    const int lane = threadIdx.x & 31;
    const int warp = threadIdx.x >> 5;
    const int wm = (warp >> 2) * 64;
    const int wn = (warp & 3) * 32;
    const int g   = lane >> 2;
    const int tig = lane & 3;

    float acc[4][4][4];
#pragma unroll
    for (int mi = 0; mi < 4; mi++)
#pragma unroll
        for (int ni = 0; ni < 4; ni++)
#pragma unroll
            for (int r = 0; r < 4; r++) acc[mi][ni][r] = 0.0f;

    tile_gemm<KDIM>(A, B, bm, bn, acc, As, Bs);

#pragma unroll
    for (int mi = 0; mi < 4; mi++) {
        int r0 = bm + wm + mi*16 + g;
        int r1 = r0 + 8;
#pragma unroll
        for (int ni = 0; ni < 4; ni++) {
            int c = bn + wn + ni*8 + tig*2;
            float bb0 = b1[c] + b2[c];
            float bb1 = b1[c+1] + b2[c+1];
            float2 v0 = make_float2(acc[mi][ni][0] + bb0, acc[mi][ni][1] + bb1);
            float2 v1 = make_float2(acc[mi][ni][2] + bb0, acc[mi][ni][3] + bb1);
            *(float2*)(Cout + (size_t)r0 * G4 + c) = v0;
            *(float2*)(Cout + (size_t)r1 * G4 + c) = v1;
        }
    }
}

// ============================================================================
// Phase-2 persistent kernel: all 16 token-LSTM steps. 128 blocks.
// ============================================================================
__global__ __launch_bounds__(256, 2) void phase2_kernel()
{
    __shared__ float As[2*128*T_PAD];
    __shared__ float Bs[2*128*T_PAD];
    const int bm = (blockIdx.x >> 3) * 128;
    const int bn = (blockIdx.x & 7) * 128;

    for (int t = 0; t < TOK; t++) {
        float acc[4][4][4];
#pragma unroll
        for (int mi = 0; mi < 4; mi++)
#pragma unroll
            for (int ni = 0; ni < 4; ni++)
#pragma unroll
                for (int r = 0; r < 4; r++) acc[mi][ni][r] = 0.0f;

        const float* Hsrc = (t & 1) ? g_H2 : g_H;
        const float* Csrc = (t & 1) ? g_C2 : g_C;
        float* Hdst = (t & 1) ? g_H : g_H2;
        float* Cdst = (t & 1) ? g_C : g_C2;

        if (t > 0) tile_gemm<HID>(Hsrc, g_WhhTokP, bm, bn, acc, As, Bs);

        fuse_epilogue(acc, bm, bn, g_Xp + (size_t)t * G4, (long)TOK * G4,
                      (t > 0) ? Csrc : nullptr, Hdst, Cdst);

        grid_sync(&g_bar2, 128u * (unsigned)(t + 1));
    }
}

// ============================================================================
// Phase-3 persistent kernel: all 16 DAG levels. 8 blocks (one n-tile each).
// ============================================================================
__global__ __launch_bounds__(256, 2) void phase3_kernel(const int* __restrict__ pidx)
{
    __shared__ float As[2*128*T_PAD];
    __shared__ float Bs[2*128*T_PAD];
    const int bn = blockIdx.x * 128;

    for (int l = 0; l < LEVELS; l++) {
        // gather: this block handles 16 rows (all 256 h)
        for (int idx = threadIdx.x; idx < 16 * HID; idx += 256) {
            int rl = idx >> 8;
            int h  = idx & 255;
            int r  = blockIdx.x * 16 + rl;      // row within level (0..127)
            int row = l * KROWS + r;
            float mh = -1e30f, mc = -1e30f;
            int has = 0;
#pragma unroll
            for (int p = 0; p < PAR; p++) {
                if (g_pval[row*PAR + p]) {
                    int pi = pidx[row*PAR + p];
                    has = 1;
                    mh = fmaxf(mh, g_Hi[(size_t)pi*HID + h]);
                    mc = fmaxf(mc, g_Ci[(size_t)pi*HID + h]);
                }
            }
            g_h0[r*HID + h] = has ? mh : 0.0f;
            g_c0[r*HID + h] = has ? mc : 0.0f;
        }
        grid_sync(&g_bar3, 8u * (unsigned)(2*l + 1));

        float acc[4][4][4];
#pragma unroll
        for (int mi = 0; mi < 4; mi++)
#pragma unroll
            for (int ni = 0; ni < 4; ni++)
#pragma unroll
                for (int r = 0; r < 4; r++) acc[mi][ni][r] = 0.0f;

        tile_gemm<HID>(g_h0, g_WhhInsP, 0, bn, acc, As, Bs);

        fuse_epilogue(acc, 0, bn, g_Gx + (size_t)l * KROWS * G4, (long)G4,
                      g_c0, g_Hi + (size_t)l * KROWS * HID, g_Ci + (size_t)l * KROWS * HID);

        grid_sync(&g_bar3, 8u * (unsigned)(2*l + 2));
    }
}

// ---------------- final: masked max over roots, then dot with Wlin ----------------
__global__ void final1_kernel()
{
    int b = blockIdx.x;
    int h = threadIdx.x;
    float m = -1e30f;
    for (int r = b*32; r < b*32 + 32; r++)
        if (g_appears[r] == 0) m = fmaxf(m, g_Hi[(size_t)r*HID + h]);
    g_partial[b*HID + h] = m;
}

__global__ void final2_kernel(const float* __restrict__ Wlin,
                              const float* __restrict__ blin,
                              float* __restrict__ out)
{
    int h = threadIdx.x;
    float m = -1e30f;
    for (int b = 0; b < 64; b++) m = fmaxf(m, g_partial[b*HID + h]);
    float v = m * Wlin[h];
    __shared__ float s[256];
    s[h] = v;
    __syncthreads();
    for (int st = 128; st > 0; st >>= 1) {
        if (h < st) s[h] += s[h + st];
        __syncthreads();
    }
    if (h == 0) out[0] = s[0] + blin[0];
}

// ---------------- launch ----------------
extern "C" void kernel_launch(void* const* d_in, const int* in_sizes, int n_in,
                              void* d_out, int out_size)
{
    const float* tokens   = (const float*)d_in[0];
    const int*   pidx     = (const int*)  d_in[1];
    const unsigned char* pval = (const unsigned char*)d_in[2];
    const float* Wih_tok  = (const float*)d_in[3];
    const float* Whh_tok  = (const float*)d_in[4];
    const float* bih_tok  = (const float*)d_in[5];
    const float* bhh_tok  = (const float*)d_in[6];
    const float* Wih_ins  = (const float*)d_in[7];
    const float* Whh_ins  = (const float*)d_in[8];
    const float* bih_ins  = (const float*)d_in[9];
    const float* bhh_ins  = (const float*)d_in[10];
    const float* Wlin     = (const float*)d_in[11];
    const float* blin     = (const float*)d_in[12];
    float* out = (float*)d_out;

    float *pXp, *pH, *pGx, *pWtP, *pWiP, *pWihTokR, *pWihInsR;
    cudaGetSymbolAddress((void**)&pXp,      g_Xp);
    cudaGetSymbolAddress((void**)&pH,       g_H);
    cudaGetSymbolAddress((void**)&pGx,      g_Gx);
    cudaGetSymbolAddress((void**)&pWtP,     g_WhhTokP);
    cudaGetSymbolAddress((void**)&pWiP,     g_WhhInsP);
    cudaGetSymbolAddress((void**)&pWihTokR, g_WihTokR);
    cudaGetSymbolAddress((void**)&pWihInsR, g_WihInsR);

    prep_kernel<<<1, 256>>>(pval, pidx);
    permW_kernel<<<G4, HID>>>(Whh_tok, pWtP);
    permW_kernel<<<G4, HID>>>(Whh_ins, pWiP);
    convW_kernel<<<(G4*EMB + 255)/256, 256>>>(Wih_tok, pWihTokR, G4*EMB);
    convW_kernel<<<(G4*HID + 255)/256, 256>>>(Wih_ins, pWihInsR, G4*HID);

    // Phase 1: Xp = tokens @ Wih_tok^T + (bih+bhh)   [32768 x 1024, K=512]
    mma_plain_kernel<EMB><<<dim3(8, 256), 256>>>(
        tokens, pWihTokR, pXp, bih_tok, bhh_tok);

    // Phase 2: persistent token-LSTM recurrence (final hidden lands in g_H)
    phase2_kernel<<<128, 256>>>();

    // Phase 3a: Gx = ins_embed @ Wih_ins^T + biases
    mma_plain_kernel<HID><<<dim3(8, 16), 256>>>(
        pH, pWihInsR, pGx, bih_ins, bhh_ins);

    // Phase 3b: persistent DAG levels
    phase3_kernel<<<8, 256>>>(pidx);

    final1_kernel<<<64, 256>>>();
    final2_kernel<<<1, 256>>>(Wlin, blin, out);
}

// round 7
// speedup vs baseline: 1.2643x; 1.2643x over previous
#include <cuda_runtime.h>
#include <math.h>
#include <stdint.h>

#define NINS   2048
#define TOK    16
#define EMB    512
#define HID    256
#define G4     (4*HID)      // 1024
#define PAR    8
#define LEVELS 16
#define KROWS  (NINS/LEVELS) // 128
#define T_PAD  20

// ---------------- scratch (static device globals; no allocation) ----------------
__device__ float g_Xp[NINS*TOK*G4];      // gate-interleaved token input projections
__device__ float g_H[NINS*HID];
__device__ float g_C[NINS*HID];
__device__ float g_H2[NINS*HID];
__device__ float g_C2[NINS*HID];
__device__ float g_Gx[NINS*G4];          // gate-interleaved
__device__ float g_Hi[NINS*HID];
__device__ float g_Ci[NINS*HID];
__device__ float g_h0[KROWS*HID];
__device__ float g_c0[KROWS*HID];
__device__ float g_WhhTokP[G4*HID];      // gate-interleaved rows, tf32-rounded
__device__ float g_WhhInsP[G4*HID];
__device__ float g_WihTokP[G4*EMB];      // gate-interleaved rows, tf32-rounded
__device__ float g_WihInsP[G4*HID];
__device__ float g_biasTokP[G4];         // permuted bih+bhh
__device__ float g_biasInsP[G4];
__device__ unsigned char g_pval[NINS*PAR];
__device__ int   g_appears[NINS];
__device__ float g_partial[64*HID];
__device__ unsigned int g_bar2;

// ---------------- helpers ----------------
__device__ __forceinline__ uint32_t cvt_tf32(float v) {
    uint32_t r;
    asm("cvt.rna.tf32.f32 %0, %1;" : "=r"(r) : "f"(v));
    return r;
}
__device__ __forceinline__ void mma_tf32(float* c, uint32_t a0, uint32_t a1,
                                         uint32_t a2, uint32_t a3,
                                         uint32_t b0, uint32_t b1) {
    asm("mma.sync.aligned.m16n8k8.row.col.f32.tf32.tf32.f32 "
        "{%0,%1,%2,%3}, {%4,%5,%6,%7}, {%8,%9}, {%0,%1,%2,%3};"
        : "+f"(c[0]), "+f"(c[1]), "+f"(c[2]), "+f"(c[3])
        : "r"(a0), "r"(a1), "r"(a2), "r"(a3), "r"(b0), "r"(b1));
}
__device__ __forceinline__ void cp_async16(void* smem, const void* gmem) {
    uint32_t s = (uint32_t)__cvta_generic_to_shared(smem);
    asm volatile("cp.async.cg.shared.global [%0], [%1], 16;\n" :: "r"(s), "l"(gmem));
}

// ---------------- grid barrier for persistent kernels ----------------
__device__ __forceinline__ void grid_sync(unsigned int* bar, unsigned int target) {
    __threadfence();
    __syncthreads();
    if (threadIdx.x == 0) {
        atomicAdd(bar, 1u);
        while (atomicAdd(bar, 0u) < target) { __nanosleep(32); }
    }
    __syncthreads();
    __threadfence();
}

// ---------------- prep ----------------
__global__ void prep_kernel(const unsigned char* __restrict__ pv_raw,
                            const int* __restrict__ pidx)
{
    __shared__ int s_hi, s_b0;
    __shared__ int s_app[NINS];
    int tid = threadIdx.x;
    if (tid == 0) { g_bar2 = 0u; }
    int hi = 0, b0 = 0;
    for (int i = 256 + tid; i < 4096; i += 256) {
        hi |= pv_raw[4*i+1] | pv_raw[4*i+2] | pv_raw[4*i+3];
        b0 |= pv_raw[4*i+0];
    }
    if (tid == 0) { s_hi = 0; s_b0 = 0; }
    __syncthreads();
    if (hi) atomicOr(&s_hi, 1);
    if (b0) atomicOr(&s_b0, 1);
    __syncthreads();
    int mode = (s_hi == 0) ? 0 : (s_b0 == 0 ? 1 : 2);
    for (int i = tid; i < NINS*PAR; i += 256) {
        unsigned char v;
        if (mode == 0)      v = (((const int*)pv_raw)[i]   != 0);
        else if (mode == 1) v = (((const float*)pv_raw)[i] != 0.0f);
        else                v = (pv_raw[i] != 0);
        g_pval[i] = v;
    }
    for (int i = tid; i < NINS; i += 256) s_app[i] = 0;
    __syncthreads();
    for (int i = tid; i < NINS*PAR; i += 256) {
        if (g_pval[i]) atomicAdd(&s_app[pidx[i]], 1);
    }
    __syncthreads();
    for (int i = tid; i < NINS; i += 256) g_appears[i] = s_app[i];
}

// permute weight rows to gate-interleave + round to tf32 (generic K)
__global__ void permW_kernel(const float* __restrict__ Win, float* __restrict__ Wout, int K)
{
    int np = blockIdx.x;
    int n  = (np & 3) * HID + (np >> 2);
    for (int c = threadIdx.x; c < K; c += 256)
        Wout[(size_t)np * K + c] = __uint_as_float(cvt_tf32(Win[(size_t)n * K + c]));
}

__global__ void permBias_kernel(const float* __restrict__ b1, const float* __restrict__ b2,
                                float* __restrict__ out)
{
    int np = blockIdx.x * 256 + threadIdx.x;
    int n  = (np & 3) * HID + (np >> 2);
    out[np] = b1[n] + b2[n];
}

// ============================================================================
// tile GEMM (mma.sync tf32, single-pass): acc += A[bm:,:K] @ B[bn:,:K]^T
// 128x128 tile, BK=16, 2-stage cp.async, 8 warps (2x4). B pre-rounded tf32.
// ============================================================================
template<int KDIM>
__device__ __forceinline__ void tile_gemm(
    const float* __restrict__ A, const float* __restrict__ B,
    int bm, int bn, float (&acc)[4][4][4], float* As, float* Bs)
{
    const int tid  = threadIdx.x;
    const int lane = tid & 31;
    const int warp = tid >> 5;
    const int wm = (warp >> 2) * 64;
    const int wn = (warp & 3) * 32;
    const int g   = lane >> 2;
    const int tig = lane & 3;
    const int NT = KDIM / 16;

#pragma unroll
    for (int u = 0; u < 2; u++) {
        int idx = u * 256 + tid;
        int r = idx >> 2, c4 = idx & 3;
        cp_async16(As + r * T_PAD + c4 * 4, A + (size_t)(bm + r) * KDIM + c4 * 4);
        cp_async16(Bs + r * T_PAD + c4 * 4, B + (size_t)(bn + r) * KDIM + c4 * 4);
    }
    asm volatile("cp.async.commit_group;\n");

    for (int kt = 0; kt < NT; kt++) {
        int cur = kt & 1;
        if (kt + 1 < NT) {
            int nxt = (kt + 1) & 1;
            const float* Ap = A + (size_t)bm * KDIM + (kt + 1) * 16;
            const float* Bp = B + (size_t)bn * KDIM + (kt + 1) * 16;
#pragma unroll
            for (int u = 0; u < 2; u++) {
                int idx = u * 256 + tid;
                int r = idx >> 2, c4 = idx & 3;
                cp_async16(As + nxt * 128 * T_PAD + r * T_PAD + c4 * 4,
                           Ap + (size_t)r * KDIM + c4 * 4);
                cp_async16(Bs + nxt * 128 * T_PAD + r * T_PAD + c4 * 4,
                           Bp + (size_t)r * KDIM + c4 * 4);
            }
            asm volatile("cp.async.commit_group;\n");
            asm volatile("cp.async.wait_group 1;\n");
        } else {
            asm volatile("cp.async.wait_group 0;\n");
        }
        __syncthreads();

        const float* Asb = As + cur * 128 * T_PAD;
        const float* Bsb = Bs + cur * 128 * T_PAD;
#pragma unroll
        for (int ks = 0; ks < 2; ks++) {
            const int k0 = ks * 8;
            uint32_t bf[4][2];
#pragma unroll
            for (int ni = 0; ni < 4; ni++) {
                bf[ni][0] = __float_as_uint(Bsb[(wn + ni*8 + g) * T_PAD + k0 + tig]);
                bf[ni][1] = __float_as_uint(Bsb[(wn + ni*8 + g) * T_PAD + k0 + tig + 4]);
            }
            uint32_t af[4][4];
#pragma unroll
            for (int mi = 0; mi < 4; mi++) {
                int r0 = (wm + mi*16 + g) * T_PAD + k0;
                int r1 = (wm + mi*16 + 8 + g) * T_PAD + k0;
                af[mi][0] = cvt_tf32(Asb[r0 + tig]);
                af[mi][1] = cvt_tf32(Asb[r1 + tig]);
                af[mi][2] = cvt_tf32(Asb[r0 + tig + 4]);
                af[mi][3] = cvt_tf32(Asb[r1 + tig + 4]);
            }
#pragma unroll
            for (int mi = 0; mi < 4; mi++)
#pragma unroll
                for (int ni = 0; ni < 4; ni++)
                    mma_tf32(acc[mi][ni], af[mi][0], af[mi][1], af[mi][2], af[mi][3],
                             bf[ni][0], bf[ni][1]);
        }
        __syncthreads();
    }
}

// fused LSTM epilogue; Add is gate-interleaved ([row][h*4+gate]) -> one float4
__device__ __forceinline__ void fuse_epilogue(
    float (&acc)[4][4][4], int bm, int bn,
    const float* __restrict__ Add, long addStride,
    const float* __restrict__ Cprev,
    float* __restrict__ Hout, float* __restrict__ Cstate)
{
    const int lane = threadIdx.x & 31;
    const int warp = threadIdx.x >> 5;
    const int wm = (warp >> 2) * 64;
    const int wn = (warp & 3) * 32;
    const int g   = lane >> 2;
    const int tig = lane & 3;
#pragma unroll
    for (int mi = 0; mi < 4; mi++) {
#pragma unroll
        for (int ni = 0; ni < 4; ni++) {
            float c0 = acc[mi][ni][0], c1 = acc[mi][ni][1];
            float c2 = acc[mi][ni][2], c3 = acc[mi][ni][3];
            float x0 = __shfl_xor_sync(0xffffffffu, c0, 1);
            float x1 = __shfl_xor_sync(0xffffffffu, c1, 1);
            float x2 = __shfl_xor_sync(0xffffffffu, c2, 1);
            float x3 = __shfl_xor_sync(0xffffffffu, c3, 1);
            int q = tig >> 1;
            int h = (bn + wn + ni*8 + q*4) >> 2;
            int row;
            float gi, gf, gg, go;
            if ((tig & 1) == 0) {
                row = bm + wm + mi*16 + g;
                gi = c0; gf = c1; gg = x0; go = x1;
            } else {
                row = bm + wm + mi*16 + 8 + g;
                gi = x2; gf = x3; gg = c2; go = c3;
            }
            const float4 ad4 = *(const float4*)(Add + (size_t)row * addStride + 4*h);
            gi += ad4.x;
            gf += ad4.y;
            gg += ad4.z;
            go += ad4.w;
            float c = Cprev ? Cprev[(size_t)row * HID + h] : 0.0f;
            float si = 1.0f / (1.0f + expf(-gi));
            float sf = 1.0f / (1.0f + expf(-gf));
            float so = 1.0f / (1.0f + expf(-go));
            float cn = sf * c + si * tanhf(gg);
            float hn = so * tanhf(cn);
            Cstate[(size_t)row * HID + h] = cn;
            Hout[(size_t)row * HID + h]   = hn;
        }
    }
}

// ============================================================================
// Plain GEMM kernel (phase-1 Xp and phase-3a Gx): C = A@B^T + bias (permuted)
// ============================================================================
template<int KDIM>
__global__ __launch_bounds__(256, 2) void mma_plain_kernel(
    const float* __restrict__ A, const float* __restrict__ B,
    float* __restrict__ Cout, const float* __restrict__ bias)
{
    __shared__ float As[2*128*T_PAD];
    __shared__ float Bs[2*128*T_PAD];
    const int bm = blockIdx.y * 128;
    const int bn = blockIdx.x * 128;
    const int lane = threadIdx.x & 31;
    const int warp = threadIdx.x >> 5;
    const int wm = (warp >> 2) * 64;
    const int wn = (warp & 3) * 32;
    const int g   = lane >> 2;
    const int tig = lane & 3;

    float acc[4][4][4];
#pragma unroll
    for (int mi = 0; mi < 4; mi++)
#pragma unroll
        for (int ni = 0; ni < 4; ni++)
#pragma unroll
            for (int r = 0; r < 4; r++) acc[mi][ni][r] = 0.0f;

    tile_gemm<KDIM>(A, B, bm, bn, acc, As, Bs);

#pragma unroll
    for (int mi = 0; mi < 4; mi++) {
        int r0 = bm + wm + mi*16 + g;
        int r1 = r0 + 8;
#pragma unroll
        for (int ni = 0; ni < 4; ni++) {
            int c = bn + wn + ni*8 + tig*2;
            float bb0 = bias[c];
            float bb1 = bias[c+1];
            float2 v0 = make_float2(acc[mi][ni][0] + bb0, acc[mi][ni][1] + bb1);
            float2 v1 = make_float2(acc[mi][ni][2] + bb0, acc[mi][ni][3] + bb1);
            *(float2*)(Cout + (size_t)r0 * G4 + c) = v0;
            *(float2*)(Cout + (size_t)r1 * G4 + c) = v1;
        }
    }
}

// ============================================================================
// Phase-2 persistent kernel: all 16 token-LSTM steps. 128 blocks.
// ============================================================================
__global__ __launch_bounds__(256, 2) void phase2_kernel()
{
    __shared__ float As[2*128*T_PAD];
    __shared__ float Bs[2*128*T_PAD];
    const int bm = (blockIdx.x >> 3) * 128;
    const int bn = (blockIdx.x & 7) * 128;

    for (int t = 0; t < TOK; t++) {
        float acc[4][4][4];
#pragma unroll
        for (int mi = 0; mi < 4; mi++)
#pragma unroll
            for (int ni = 0; ni < 4; ni++)
#pragma unroll
                for (int r = 0; r < 4; r++) acc[mi][ni][r] = 0.0f;

        const float* Hsrc = (t & 1) ? g_H2 : g_H;
        const float* Csrc = (t & 1) ? g_C2 : g_C;
        float* Hdst = (t & 1) ? g_H : g_H2;
        float* Cdst = (t & 1) ? g_C : g_C2;

        if (t > 0) tile_gemm<HID>(Hsrc, g_WhhTokP, bm, bn, acc, As, Bs);

        fuse_epilogue(acc, bm, bn, g_Xp + (size_t)t * G4, (long)TOK * G4,
                      (t > 0) ? Csrc : nullptr, Hdst, Cdst);

        grid_sync(&g_bar2, 128u * (unsigned)(t + 1));
    }
}

// ---------------- per-level parent gather (max combine) ----------------
__global__ void gather_kernel(const int* __restrict__ pidx, int l)
{
    int r   = blockIdx.x;
    int row = l * KROWS + r;
    int h   = threadIdx.x;
    __shared__ int sp[PAR];
    __shared__ int sv[PAR];
    if (h < PAR) {
        sp[h] = pidx[row*PAR + h];
        sv[h] = g_pval[row*PAR + h];
    }
    __syncthreads();
    float mh = -1e30f, mc = -1e30f;
    int has = 0;
#pragma unroll
    for (int p = 0; p < PAR; p++) {
        if (sv[p]) {
            has = 1;
            mh = fmaxf(mh, g_Hi[(size_t)sp[p]*HID + h]);
            mc = fmaxf(mc, g_Ci[(size_t)sp[p]*HID + h]);
        }
    }
    g_h0[r*HID + h] = has ? mh : 0.0f;
    g_c0[r*HID + h] = has ? mc : 0.0f;
}

// per-level fused GEMM+LSTM (8 blocks, M=128)
__global__ __launch_bounds__(256, 2) void level_kernel(int l)
{
    __shared__ float As[2*128*T_PAD];
    __shared__ float Bs[2*128*T_PAD];
    const int bn = blockIdx.x * 128;
    float acc[4][4][4];
#pragma unroll
    for (int mi = 0; mi < 4; mi++)
#pragma unroll
        for (int ni = 0; ni < 4; ni++)
#pragma unroll
            for (int r = 0; r < 4; r++) acc[mi][ni][r] = 0.0f;

    tile_gemm<HID>(g_h0, g_WhhInsP, 0, bn, acc, As, Bs);
    fuse_epilogue(acc, 0, bn, g_Gx + (size_t)l * KROWS * G4, (long)G4,
                  g_c0, g_Hi + (size_t)l * KROWS * HID, g_Ci + (size_t)l * KROWS * HID);
}

// ---------------- final: masked max over roots, then dot with Wlin ----------------
__global__ void final1_kernel()
{
    int b = blockIdx.x;
    int h = threadIdx.x;
    float m = -1e30f;
    for (int r = b*32; r < b*32 + 32; r++)
        if (g_appears[r] == 0) m = fmaxf(m, g_Hi[(size_t)r*HID + h]);
    g_partial[b*HID + h] = m;
}

__global__ void final2_kernel(const float* __restrict__ Wlin,
                              const float* __restrict__ blin,
                              float* __restrict__ out)
{
    int h = threadIdx.x;
    float m = -1e30f;
    for (int b = 0; b < 64; b++) m = fmaxf(m, g_partial[b*HID + h]);
    float v = m * Wlin[h];
    __shared__ float s[256];
    s[h] = v;
    __syncthreads();
    for (int st = 128; st > 0; st >>= 1) {
        if (h < st) s[h] += s[h + st];
        __syncthreads();
    }
    if (h == 0) out[0] = s[0] + blin[0];
}

// ---------------- launch ----------------
extern "C" void kernel_launch(void* const* d_in, const int* in_sizes, int n_in,
                              void* d_out, int out_size)
{
    const float* tokens   = (const float*)d_in[0];
    const int*   pidx     = (const int*)  d_in[1];
    const unsigned char* pval = (const unsigned char*)d_in[2];
    const float* Wih_tok  = (const float*)d_in[3];
    const float* Whh_tok  = (const float*)d_in[4];
    const float* bih_tok  = (const float*)d_in[5];
    const float* bhh_tok  = (const float*)d_in[6];
    const float* Wih_ins  = (const float*)d_in[7];
    const float* Whh_ins  = (const float*)d_in[8];
    const float* bih_ins  = (const float*)d_in[9];
    const float* bhh_ins  = (const float*)d_in[10];
    const float* Wlin     = (const float*)d_in[11];
    const float* blin     = (const float*)d_in[12];
    float* out = (float*)d_out;

    float *pXp, *pH, *pGx, *pWihTokP, *pWihInsP, *pBT, *pBI, *pWtP, *pWiP;
    cudaGetSymbolAddress((void**)&pXp,      g_Xp);
    cudaGetSymbolAddress((void**)&pH,       g_H);
    cudaGetSymbolAddress((void**)&pGx,      g_Gx);
    cudaGetSymbolAddress((void**)&pWtP,     g_WhhTokP);
    cudaGetSymbolAddress((void**)&pWiP,     g_WhhInsP);
    cudaGetSymbolAddress((void**)&pWihTokP, g_WihTokP);
    cudaGetSymbolAddress((void**)&pWihInsP, g_WihInsP);
    cudaGetSymbolAddress((void**)&pBT,      g_biasTokP);
    cudaGetSymbolAddress((void**)&pBI,      g_biasInsP);

    prep_kernel<<<1, 256>>>(pval, pidx);
    permW_kernel<<<G4, 256>>>(Whh_tok, pWtP, HID);
    permW_kernel<<<G4, 256>>>(Whh_ins, pWiP, HID);
    permW_kernel<<<G4, 256>>>(Wih_tok, pWihTokP, EMB);
    permW_kernel<<<G4, 256>>>(Wih_ins, pWihInsP, HID);
    permBias_kernel<<<4, 256>>>(bih_tok, bhh_tok, pBT);
    permBias_kernel<<<4, 256>>>(bih_ins, bhh_ins, pBI);

    // Phase 1: Xp (gate-interleaved) = tokens @ WihTokP^T + biasTokP
    mma_plain_kernel<EMB><<<dim3(8, 256), 256>>>(tokens, pWihTokP, pXp, pBT);

    // Phase 2: persistent token-LSTM recurrence (final hidden lands in g_H)
    phase2_kernel<<<128, 256>>>();

    // Phase 3a: Gx (gate-interleaved) = ins_embed @ WihInsP^T + biasInsP
    mma_plain_kernel<HID><<<dim3(8, 16), 256>>>(pH, pWihInsP, pGx, pBI);

    // Phase 3b: per-level gather (wide) + fused GEMM+LSTM
    for (int l = 0; l < LEVELS; l++) {
        gather_kernel<<<KROWS, HID>>>(pidx, l);
        level_kernel<<<8, 256>>>(l);
    }

    final1_kernel<<<64, 256>>>();
    final2_kernel<<<1, 256>>>(Wlin, blin, out);
}